// round 5
// baseline (speedup 1.0000x reference)
#include <cuda_runtime.h>
#include <math.h>

// ---------------------------------------------------------------------------
// MTCNN P-net pyramid, B=4, 1080x1080x3 input, 12 scales.
// Pipeline per scale (all NHWC, fp32):
//   resize_h  (antialiased triangle, horizontal)  -> g_tmpH [4,1080,ws,3]
//   resize_v  (vertical + (x-127.5)/128)          -> g_img  [4,hs,ws,3]
//   conv3x3 3->10 + lrelu(0.3)                    -> g_c1
//   maxpool 2x2 s2 SAME                           -> g_p1
//   conv3x3 10->16 + lrelu                        -> g_c2
//   conv3x3 16->32 + lrelu                        -> g_c3
//   heads: softmax score, 4-ch reg, boxes, mask   -> d_out (boxes|reg|mask)
// ---------------------------------------------------------------------------

#define BATCH 4
#define HIN 1080

// Scratch sized for scale 0 (hs=648 -> h1=646, h2=323, h3=321, h4=319)
__device__ float g_tmpH[BATCH * 1080 * 648 * 3];   // horizontal-pass intermediate
__device__ float g_img [BATCH * 648  * 648 * 3];   // resized+normalized image
__device__ float g_c1  [BATCH * 646  * 646 * 10];
__device__ float g_p1  [BATCH * 323  * 323 * 10];
__device__ float g_c2  [BATCH * 321  * 321 * 16];
__device__ float g_c3  [BATCH * 319  * 319 * 32];

// ---------------------------------------------------------------------------
// Anti-aliased separable resize (matches jax.image.resize 'bilinear',
// antialias=True, downscale only): sample_f = (i+0.5)*(in/out)-0.5,
// triangle kernel with width = in/out, per-output normalization.
// ---------------------------------------------------------------------------
__global__ void k_resize_h(const float* __restrict__ in, int ws, float inv)
{
    int idx = blockIdx.x * blockDim.x + threadIdx.x;
    int total = BATCH * HIN * ws;
    if (idx >= total) return;
    int ox = idx % ws;
    int by = idx / ws;                       // b*1080 + y
    float sf = (ox + 0.5f) * inv - 0.5f;
    int j0 = (int)ceilf(sf - inv);  if (j0 < 0) j0 = 0;
    int j1 = (int)floorf(sf + inv); if (j1 > HIN - 1) j1 = HIN - 1;
    float a0 = 0.f, a1 = 0.f, a2 = 0.f, wsum = 0.f;
    const float* row = in + (size_t)by * HIN * 3;
    for (int j = j0; j <= j1; j++) {
        float wv = fmaxf(1.f - fabsf(sf - (float)j) / inv, 0.f);
        wsum += wv;
        a0 = fmaf(wv, row[j * 3 + 0], a0);
        a1 = fmaf(wv, row[j * 3 + 1], a1);
        a2 = fmaf(wv, row[j * 3 + 2], a2);
    }
    float s = 1.f / wsum;
    float* o = g_tmpH + (size_t)idx * 3;
    o[0] = a0 * s; o[1] = a1 * s; o[2] = a2 * s;
}

__global__ void k_resize_v(int hs, int ws, float inv)
{
    int idx = blockIdx.x * blockDim.x + threadIdx.x;
    int total = BATCH * hs * ws;
    if (idx >= total) return;
    int x  = idx % ws;
    int t  = idx / ws;
    int oy = t % hs;
    int b  = t / hs;
    float sf = (oy + 0.5f) * inv - 0.5f;
    int j0 = (int)ceilf(sf - inv);  if (j0 < 0) j0 = 0;
    int j1 = (int)floorf(sf + inv); if (j1 > HIN - 1) j1 = HIN - 1;
    float a0 = 0.f, a1 = 0.f, a2 = 0.f, wsum = 0.f;
    for (int j = j0; j <= j1; j++) {
        float wv = fmaxf(1.f - fabsf(sf - (float)j) / inv, 0.f);
        wsum += wv;
        const float* p = g_tmpH + ((size_t)(b * HIN + j) * ws + x) * 3;
        a0 = fmaf(wv, p[0], a0);
        a1 = fmaf(wv, p[1], a1);
        a2 = fmaf(wv, p[2], a2);
    }
    float s = 1.f / wsum;
    float* o = g_img + ((size_t)(b * hs + oy) * ws + x) * 3;
    o[0] = (a0 * s - 127.5f) * (1.f / 128.f);
    o[1] = (a1 * s - 127.5f) * (1.f / 128.f);
    o[2] = (a2 * s - 127.5f) * (1.f / 128.f);
}

// ---------------------------------------------------------------------------
// 3x3 VALID conv + LeakyReLU(0.3). Weights HWIO in SMEM (broadcast LDS).
// Each thread computes TX consecutive x-positions, all OC channels.
// ---------------------------------------------------------------------------
template<int IC, int OC, int TX>
__device__ __forceinline__ void conv3x3_lrelu_body(
    const float* __restrict__ in, const float* __restrict__ w,
    const float* __restrict__ bias, float* __restrict__ out,
    int hin, int win)
{
    const int hout = hin - 2, wout = win - 2;
    const int WG = (wout + TX - 1) / TX;
    __shared__ float ws_[9 * IC * OC];
    __shared__ float bs_[OC];
    for (int i = threadIdx.x; i < 9 * IC * OC; i += blockDim.x) ws_[i] = w[i];
    if (threadIdx.x < OC) bs_[threadIdx.x] = bias[threadIdx.x];
    __syncthreads();

    int idx = blockIdx.x * blockDim.x + threadIdx.x;
    if (idx >= BATCH * hout * WG) return;
    int xg = idx % WG;
    int t2 = idx / WG;
    int y  = t2 % hout;
    int b  = t2 / hout;
    int x0 = xg * TX;

    float acc[TX][OC];
#pragma unroll
    for (int t = 0; t < TX; t++)
#pragma unroll
        for (int oc = 0; oc < OC; oc++) acc[t][oc] = bs_[oc];

    const float* base = in + ((size_t)(b * hin + y) * win) * IC;
#pragma unroll
    for (int ky = 0; ky < 3; ky++) {
        const float* rowp = base + (size_t)ky * win * IC;
        for (int ic = 0; ic < IC; ic++) {
            float v[TX + 2];
#pragma unroll
            for (int t = 0; t < TX + 2; t++) {
                int xx = x0 + t; if (xx > win - 1) xx = win - 1;
                v[t] = __ldg(rowp + (size_t)xx * IC + ic);
            }
#pragma unroll
            for (int kx = 0; kx < 3; kx++) {
                const float* wp = ws_ + ((ky * 3 + kx) * IC + ic) * OC;
#pragma unroll
                for (int oc = 0; oc < OC; oc++) {
                    float wv = wp[oc];
#pragma unroll
                    for (int t = 0; t < TX; t++)
                        acc[t][oc] = fmaf(v[t + kx], wv, acc[t][oc]);
                }
            }
        }
    }
#pragma unroll
    for (int t = 0; t < TX; t++) {
        int x = x0 + t;
        if (x < wout) {
            float* op = out + ((size_t)(b * hout + y) * wout + x) * OC;
#pragma unroll
            for (int oc = 0; oc < OC; oc++) {
                float z = acc[t][oc];
                op[oc] = z > 0.f ? z : 0.3f * z;
            }
        }
    }
}

__global__ void k_conv1(const float* __restrict__ w, const float* __restrict__ b,
                        int hin, int win)
{ conv3x3_lrelu_body<3, 10, 4>(g_img, w, b, g_c1, hin, win); }

__global__ void k_conv2(const float* __restrict__ w, const float* __restrict__ b,
                        int hin, int win)
{ conv3x3_lrelu_body<10, 16, 4>(g_p1, w, b, g_c2, hin, win); }

__global__ void k_conv3(const float* __restrict__ w, const float* __restrict__ b,
                        int hin, int win)
{ conv3x3_lrelu_body<16, 32, 2>(g_c2, w, b, g_c3, hin, win); }

// ---------------------------------------------------------------------------
// 2x2 stride-2 maxpool, SAME (pad_lo=0, pad_hi = in&1).
// ---------------------------------------------------------------------------
__global__ void k_pool(int hin, int win)
{
    int hout = (hin + 1) / 2, wout = (win + 1) / 2;
    int idx = blockIdx.x * blockDim.x + threadIdx.x;
    if (idx >= BATCH * hout * wout) return;
    int x = idx % wout;
    int t = idx / wout;
    int y = t % hout;
    int b = t / hout;
    int y0 = 2 * y, x0 = 2 * x;
    int y1 = y0 + 1 < hin ? y0 + 1 : hin - 1;
    int x1 = x0 + 1 < win ? x0 + 1 : win - 1;
    const float* p00 = g_c1 + ((size_t)(b * hin + y0) * win + x0) * 10;
    const float* p01 = g_c1 + ((size_t)(b * hin + y0) * win + x1) * 10;
    const float* p10 = g_c1 + ((size_t)(b * hin + y1) * win + x0) * 10;
    const float* p11 = g_c1 + ((size_t)(b * hin + y1) * win + x1) * 10;
    float* o = g_p1 + ((size_t)(b * hout + y) * wout + x) * 10;
#pragma unroll
    for (int c = 0; c < 10; c++)
        o[c] = fmaxf(fmaxf(p00[c], p01[c]), fmaxf(p10[c], p11[c]));
}

// ---------------------------------------------------------------------------
// Heads: 1x1 convs (32->2 softmax, 32->4 reg), grid boxes, mask.
// Output layout: boxes[4][N][5] | reg[4][N][4] | mask[4][N]   (all f32)
// ---------------------------------------------------------------------------
__global__ void k_head(const float* __restrict__ wp, const float* __restrict__ bp,
                       const float* __restrict__ wr, const float* __restrict__ br,
                       float* __restrict__ out,
                       int h, int w, int noff, int ntot, float scale)
{
    __shared__ float swp[64], swr[128], sb[6];
    if (threadIdx.x < 64)  swp[threadIdx.x] = wp[threadIdx.x];
    if (threadIdx.x >= 64 && threadIdx.x < 192) swr[threadIdx.x - 64] = wr[threadIdx.x - 64];
    if (threadIdx.x == 192) { sb[0] = bp[0]; sb[1] = bp[1]; }
    if (threadIdx.x == 193) { sb[2] = br[0]; sb[3] = br[1]; sb[4] = br[2]; sb[5] = br[3]; }
    __syncthreads();

    int idx = blockIdx.x * blockDim.x + threadIdx.x;
    if (idx >= BATCH * h * w) return;
    int x = idx % w;
    int t = idx / w;
    int y = t % h;
    int b = t / h;

    const float* v = g_c3 + ((size_t)(b * h + y) * w + x) * 32;
    float z0 = sb[0], z1 = sb[1];
    float r0 = sb[2], r1 = sb[3], r2 = sb[4], r3 = sb[5];
#pragma unroll
    for (int i = 0; i < 32; i++) {
        float vi = v[i];
        z0 = fmaf(vi, swp[i * 2 + 0], z0);
        z1 = fmaf(vi, swp[i * 2 + 1], z1);
        r0 = fmaf(vi, swr[i * 4 + 0], r0);
        r1 = fmaf(vi, swr[i * 4 + 1], r1);
        r2 = fmaf(vi, swr[i * 4 + 2], r2);
        r3 = fmaf(vi, swr[i * 4 + 3], r3);
    }
    float score = 1.f / (1.f + expf(z0 - z1));   // softmax channel 1

    int n = noff + y * w + x;
    float fy = (float)y, fx = (float)x;
    float ulr = rintf((fy * 2.f + 1.f)  / scale);
    float ulc = rintf((fx * 2.f + 1.f)  / scale);
    float drr = rintf((fy * 2.f + 12.f) / scale);
    float drc = rintf((fx * 2.f + 12.f) / scale);

    float* pb = out + ((size_t)b * ntot + n) * 5;
    pb[0] = ulr; pb[1] = ulc; pb[2] = drr; pb[3] = drc; pb[4] = score;

    float* pr = out + (size_t)BATCH * ntot * 5 + ((size_t)b * ntot + n) * 4;
    pr[0] = r0; pr[1] = r1; pr[2] = r2; pr[3] = r3;

    out[(size_t)BATCH * ntot * 9 + (size_t)b * ntot + n] = (score >= 0.6f) ? 1.f : 0.f;
}

// ---------------------------------------------------------------------------
extern "C" void kernel_launch(void* const* d_in, const int* in_sizes, int n_in,
                              void* d_out, int out_size)
{
    const float* inp = (const float*)d_in[0];
    const float* w1  = (const float*)d_in[1];
    const float* b1  = (const float*)d_in[2];
    const float* w2  = (const float*)d_in[3];
    const float* b2  = (const float*)d_in[4];
    const float* w3  = (const float*)d_in[5];
    const float* b3  = (const float*)d_in[6];
    const float* wp  = (const float*)d_in[7];
    const float* bp  = (const float*)d_in[8];
    const float* wr  = (const float*)d_in[9];
    const float* br  = (const float*)d_in[10];
    float* out = (float*)d_out;
    (void)in_sizes; (void)n_in; (void)out_size;

    // Scale pyramid (double recurrence, matches reference get_scales()).
    double sc[16]; int hss[16]; int ns = 0;
    {
        double s = 12.0 / 20.0, m = s * 1080.0;
        while (m >= 12.0 && ns < 16) {
            sc[ns] = s;
            hss[ns] = (int)ceil(1080.0 * s);
            ns++;
            s *= 0.709; m *= 0.709;
        }
    }
    int ntot = 0, noffs[16];
    for (int k = 0; k < ns; k++) {
        int h4 = ((hss[k] - 1) / 2) - 4;     // ceil((hs-2)/2) - 4
        noffs[k] = ntot;
        ntot += h4 * h4;
    }

    for (int k = 0; k < ns; k++) {
        int hs = hss[k], ws = hs;
        float inv = (float)(1080.0 / (double)hs);   // in/out for both dims

        int T = BATCH * HIN * ws;
        k_resize_h<<<(T + 255) / 256, 256>>>(inp, ws, inv);
        T = BATCH * hs * ws;
        k_resize_v<<<(T + 255) / 256, 256>>>(hs, ws, inv);

        int h1 = hs - 2, w1d = ws - 2;
        { int WG = (w1d + 3) / 4; T = BATCH * h1 * WG;
          k_conv1<<<(T + 127) / 128, 128>>>(w1, b1, hs, ws); }

        int h2 = (h1 + 1) / 2, w2d = (w1d + 1) / 2;
        T = BATCH * h2 * w2d;
        k_pool<<<(T + 255) / 256, 256>>>(h1, w1d);

        int h3 = h2 - 2, w3d = w2d - 2;
        { int WG = (w3d + 3) / 4; T = BATCH * h3 * WG;
          k_conv2<<<(T + 127) / 128, 128>>>(w2, b2, h2, w2d); }

        int h4 = h3 - 2, w4 = w3d - 2;
        { int WG = (w4 + 1) / 2; T = BATCH * h4 * WG;
          k_conv3<<<(T + 127) / 128, 128>>>(w3, b3, h3, w3d); }

        T = BATCH * h4 * w4;
        k_head<<<(T + 255) / 256, 256>>>(wp, bp, wr, br, out,
                                         h4, w4, noffs[k], ntot, (float)sc[k]);
    }
}

// round 6
// speedup vs baseline: 2.1949x; 2.1949x over previous
#include <cuda_runtime.h>
#include <math.h>

// ---------------------------------------------------------------------------
// MTCNN P-net pyramid, B=4, 1080x1080x3, 12 scales.
// R5: 5 mega-kernels (one per stage, each covers all scales):
//   1) resize_h   (antialiased triangle, horizontal)
//   2) resize_v   (vertical + normalize)
//   3) conv1(3->10)+lrelu fused with 2x2 maxpool
//   4) conv2(10->16)+lrelu
//   5) conv3(16->32)+lrelu fused with softmax/reg heads + boxes + mask
// Per-scale scratch = disjoint partitions of static device arrays.
// ---------------------------------------------------------------------------

#define BATCH 4
#define HIN 1080
#define NS 12

__device__ float g_tmpH[28460160 + 1024];  // sum_k 4*1080*ws_k*3
__device__ float g_img [10145112 + 1024];  // sum_k 4*hs*ws*3
__device__ float g_p1  [ 8377240 + 1024];  // sum_k 4*h2*w2*10
__device__ float g_c2  [13127872 + 1024];  // sum_k 4*h3*w3*16

struct Meta {
    int   hs[NS];
    float inv[NS];
    float scl[NS];
    int   offT[NS], offI[NS], offP[NS], offC[NS];
    int   noff[NS];
    int   ntot;
    int   bsRH[NS + 1], bsRV[NS + 1], bsCP[NS + 1], bsC2[NS + 1], bsC3[NS + 1];
};

__device__ __forceinline__ int fscale(const int* bs)
{
    int k = 0;
#pragma unroll
    for (int i = 1; i < NS; i++)
        if ((int)blockIdx.x >= bs[i]) k = i;
    return k;
}

// ---------------------------------------------------------------------------
// Stage 1: horizontal antialiased resize.  in [4,1080,1080,3] -> tmpH [4,1080,ws,3]
// ---------------------------------------------------------------------------
__global__ void k_resize_h(const float* __restrict__ in, Meta m)
{
    int k = fscale(m.bsRH);
    int ws = m.hs[k];
    float inv = m.inv[k];
    int idx = (blockIdx.x - m.bsRH[k]) * blockDim.x + threadIdx.x;
    int total = BATCH * HIN * ws;
    if (idx >= total) return;
    int ox = idx % ws;
    int by = idx / ws;
    float sf = (ox + 0.5f) * inv - 0.5f;
    int j0 = (int)ceilf(sf - inv);  if (j0 < 0) j0 = 0;
    int j1 = (int)floorf(sf + inv); if (j1 > HIN - 1) j1 = HIN - 1;
    float a0 = 0.f, a1 = 0.f, a2 = 0.f, wsum = 0.f;
    const float* row = in + (size_t)by * HIN * 3;
    for (int j = j0; j <= j1; j++) {
        float wv = fmaxf(1.f - fabsf(sf - (float)j) / inv, 0.f);
        wsum += wv;
        a0 = fmaf(wv, row[j * 3 + 0], a0);
        a1 = fmaf(wv, row[j * 3 + 1], a1);
        a2 = fmaf(wv, row[j * 3 + 2], a2);
    }
    float s = 1.f / wsum;
    float* o = g_tmpH + m.offT[k] + (size_t)idx * 3;
    o[0] = a0 * s; o[1] = a1 * s; o[2] = a2 * s;
}

// ---------------------------------------------------------------------------
// Stage 2: vertical resize + (x-127.5)/128.  tmpH -> img [4,hs,ws,3]
// ---------------------------------------------------------------------------
__global__ void k_resize_v(Meta m)
{
    int k = fscale(m.bsRV);
    int hs = m.hs[k], ws = hs;
    float inv = m.inv[k];
    int idx = (blockIdx.x - m.bsRV[k]) * blockDim.x + threadIdx.x;
    int total = BATCH * hs * ws;
    if (idx >= total) return;
    int x  = idx % ws;
    int t  = idx / ws;
    int oy = t % hs;
    int b  = t / hs;
    float sf = (oy + 0.5f) * inv - 0.5f;
    int j0 = (int)ceilf(sf - inv);  if (j0 < 0) j0 = 0;
    int j1 = (int)floorf(sf + inv); if (j1 > HIN - 1) j1 = HIN - 1;
    float a0 = 0.f, a1 = 0.f, a2 = 0.f, wsum = 0.f;
    const float* base = g_tmpH + m.offT[k];
    for (int j = j0; j <= j1; j++) {
        float wv = fmaxf(1.f - fabsf(sf - (float)j) / inv, 0.f);
        wsum += wv;
        const float* p = base + ((size_t)(b * HIN + j) * ws + x) * 3;
        a0 = fmaf(wv, p[0], a0);
        a1 = fmaf(wv, p[1], a1);
        a2 = fmaf(wv, p[2], a2);
    }
    float s = 1.f / wsum;
    float* o = g_img + m.offI[k] + ((size_t)(b * hs + oy) * ws + x) * 3;
    o[0] = (a0 * s - 127.5f) * (1.f / 128.f);
    o[1] = (a1 * s - 127.5f) * (1.f / 128.f);
    o[2] = (a2 * s - 127.5f) * (1.f / 128.f);
}

// ---------------------------------------------------------------------------
// Stage 3: conv3x3 3->10 + lrelu fused with 2x2/2 maxpool (SAME, -inf pad).
// One thread per pooled pixel: compute the 2x2 conv block in regs, max.
// ---------------------------------------------------------------------------
__global__ void __launch_bounds__(128)
k_conv1pool(const float* __restrict__ w, const float* __restrict__ bias, Meta m)
{
    __shared__ float ws_[270], bs_[10];
    for (int i = threadIdx.x; i < 270; i += blockDim.x) ws_[i] = w[i];
    if (threadIdx.x < 10) bs_[threadIdx.x] = bias[threadIdx.x];
    __syncthreads();

    int k = fscale(m.bsCP);
    int hs = m.hs[k], ws = hs;
    int h1 = hs - 2, w1 = ws - 2;
    int h2 = (h1 + 1) >> 1, w2 = (w1 + 1) >> 1;
    int idx = (blockIdx.x - m.bsCP[k]) * blockDim.x + threadIdx.x;
    if (idx >= BATCH * h2 * w2) return;
    int x = idx % w2;
    int t = idx / w2;
    int y = t % h2;
    int b = t / h2;

    const float* img = g_img + m.offI[k];
    int r0 = 2 * y, c0 = 2 * x;
    bool vr = (r0 + 1 < h1), vc = (c0 + 1 < w1);

    // 4x4x3 input patch (clamped loads; clamped entries unused by valid convs)
    float pr[4][4][3];
#pragma unroll
    for (int i = 0; i < 4; i++) {
        int ry = r0 + i; if (ry > hs - 1) ry = hs - 1;
        const float* rp = img + (size_t)(b * hs + ry) * ws * 3;
#pragma unroll
        for (int j = 0; j < 4; j++) {
            int cx = c0 + j; if (cx > ws - 1) cx = ws - 1;
            const float* p = rp + (size_t)cx * 3;
            pr[i][j][0] = __ldg(p + 0);
            pr[i][j][1] = __ldg(p + 1);
            pr[i][j][2] = __ldg(p + 2);
        }
    }

    // 4 conv pixels accumulated simultaneously (shared weight reads)
    float tmp[4][10];
#pragma unroll
    for (int p = 0; p < 4; p++)
#pragma unroll
        for (int oc = 0; oc < 10; oc++) tmp[p][oc] = bs_[oc];

#pragma unroll
    for (int ky = 0; ky < 3; ky++)
#pragma unroll
    for (int kx = 0; kx < 3; kx++)
#pragma unroll
    for (int ic = 0; ic < 3; ic++) {
        const float2* wq = (const float2*)(ws_ + ((ky * 3 + kx) * 3 + ic) * 10);
        float v00 = pr[ky][kx][ic],     v01 = pr[ky][kx + 1][ic];
        float v10 = pr[ky + 1][kx][ic], v11 = pr[ky + 1][kx + 1][ic];
#pragma unroll
        for (int o2 = 0; o2 < 5; o2++) {
            float2 wv = wq[o2];
            tmp[0][o2*2+0] = fmaf(v00, wv.x, tmp[0][o2*2+0]);
            tmp[0][o2*2+1] = fmaf(v00, wv.y, tmp[0][o2*2+1]);
            tmp[1][o2*2+0] = fmaf(v01, wv.x, tmp[1][o2*2+0]);
            tmp[1][o2*2+1] = fmaf(v01, wv.y, tmp[1][o2*2+1]);
            tmp[2][o2*2+0] = fmaf(v10, wv.x, tmp[2][o2*2+0]);
            tmp[2][o2*2+1] = fmaf(v10, wv.y, tmp[2][o2*2+1]);
            tmp[3][o2*2+0] = fmaf(v11, wv.x, tmp[3][o2*2+0]);
            tmp[3][o2*2+1] = fmaf(v11, wv.y, tmp[3][o2*2+1]);
        }
    }

    float pa[10];
#pragma unroll
    for (int oc = 0; oc < 10; oc++) {
        float z = tmp[0][oc];
        float a = z > 0.f ? z : 0.3f * z;        // pixel (0,0) always valid
        if (vc) { z = tmp[1][oc]; a = fmaxf(a, z > 0.f ? z : 0.3f * z); }
        if (vr) { z = tmp[2][oc]; a = fmaxf(a, z > 0.f ? z : 0.3f * z); }
        if (vr && vc) { z = tmp[3][oc]; a = fmaxf(a, z > 0.f ? z : 0.3f * z); }
        pa[oc] = a;
    }

    float2* o = (float2*)(g_p1 + m.offP[k] + ((size_t)(b * h2 + y) * w2 + x) * 10);
#pragma unroll
    for (int o2 = 0; o2 < 5; o2++)
        o[o2] = make_float2(pa[o2 * 2], pa[o2 * 2 + 1]);
}

// ---------------------------------------------------------------------------
// Stage 4: conv3x3 10->16 + lrelu.  Thread computes TX=4 x-positions.
// ---------------------------------------------------------------------------
__global__ void __launch_bounds__(128)
k_conv2(const float* __restrict__ w, const float* __restrict__ bias, Meta m)
{
    __shared__ float ws_[1440], bs_[16];
    {
        const float4* s4 = (const float4*)w;
        float4* d4 = (float4*)ws_;
        for (int i = threadIdx.x; i < 360; i += blockDim.x) d4[i] = s4[i];
        if (threadIdx.x < 16) bs_[threadIdx.x] = bias[threadIdx.x];
    }
    __syncthreads();

    int k = fscale(m.bsC2);
    int hs = m.hs[k];
    int hin = (hs - 1) >> 1, win = hin;      // h2
    int hout = hin - 2, wout = win - 2;      // h3
    int WG = (wout + 3) >> 2;
    int idx = (blockIdx.x - m.bsC2[k]) * blockDim.x + threadIdx.x;
    if (idx >= BATCH * hout * WG) return;
    int xg = idx % WG;
    int t2 = idx / WG;
    int y  = t2 % hout;
    int b  = t2 / hout;
    int x0 = xg * 4;

    float acc[4][16];
#pragma unroll
    for (int t = 0; t < 4; t++)
#pragma unroll
        for (int oc = 0; oc < 16; oc++) acc[t][oc] = bs_[oc];

    const float* base = g_p1 + m.offP[k] + (size_t)(b * hin + y) * win * 10;
#pragma unroll
    for (int ky = 0; ky < 3; ky++) {
        const float* rowp = base + (size_t)ky * win * 10;
        for (int ic = 0; ic < 10; ic++) {
            float v[6];
#pragma unroll
            for (int t = 0; t < 6; t++) {
                int xx = x0 + t; if (xx > win - 1) xx = win - 1;
                v[t] = __ldg(rowp + (size_t)xx * 10 + ic);
            }
#pragma unroll
            for (int kx = 0; kx < 3; kx++) {
                const float4* wq = (const float4*)(ws_ + ((ky * 3 + kx) * 10 + ic) * 16);
#pragma unroll
                for (int o4 = 0; o4 < 4; o4++) {
                    float4 wv = wq[o4];
#pragma unroll
                    for (int t = 0; t < 4; t++) {
                        acc[t][o4*4+0] = fmaf(v[t + kx], wv.x, acc[t][o4*4+0]);
                        acc[t][o4*4+1] = fmaf(v[t + kx], wv.y, acc[t][o4*4+1]);
                        acc[t][o4*4+2] = fmaf(v[t + kx], wv.z, acc[t][o4*4+2]);
                        acc[t][o4*4+3] = fmaf(v[t + kx], wv.w, acc[t][o4*4+3]);
                    }
                }
            }
        }
    }

    float* outb = g_c2 + m.offC[k];
#pragma unroll
    for (int t = 0; t < 4; t++) {
        int x = x0 + t;
        if (x < wout) {
            float4* op = (float4*)(outb + ((size_t)(b * hout + y) * wout + x) * 16);
#pragma unroll
            for (int o4 = 0; o4 < 4; o4++) {
                float z0 = acc[t][o4*4+0], z1 = acc[t][o4*4+1];
                float z2 = acc[t][o4*4+2], z3 = acc[t][o4*4+3];
                op[o4] = make_float4(z0 > 0.f ? z0 : 0.3f * z0,
                                     z1 > 0.f ? z1 : 0.3f * z1,
                                     z2 > 0.f ? z2 : 0.3f * z2,
                                     z3 > 0.f ? z3 : 0.3f * z3);
            }
        }
    }
}

// ---------------------------------------------------------------------------
// Stage 5: conv3x3 16->32 + lrelu fused with heads (softmax score, reg),
// box grid + mask, writing d_out directly. Thread computes TX=2 x-positions.
// Output layout: boxes[4][N][5] | reg[4][N][4] | mask[4][N]
// ---------------------------------------------------------------------------
__global__ void __launch_bounds__(128)
k_conv3head(const float* __restrict__ w, const float* __restrict__ bias,
            const float* __restrict__ wp, const float* __restrict__ bp,
            const float* __restrict__ wr, const float* __restrict__ br,
            float* __restrict__ out, Meta m)
{
    __shared__ float ws_[4608], cb_[32], hwp[64], hwr[128], hb[6];
    {
        const float4* s4 = (const float4*)w;
        float4* d4 = (float4*)ws_;
        for (int i = threadIdx.x; i < 1152; i += blockDim.x) d4[i] = s4[i];
        if (threadIdx.x < 32) cb_[threadIdx.x] = bias[threadIdx.x];
        if (threadIdx.x < 64) hwp[threadIdx.x] = wp[threadIdx.x];
        hwr[threadIdx.x] = wr[threadIdx.x];
        if (threadIdx.x == 64) { hb[0] = bp[0]; hb[1] = bp[1]; }
        if (threadIdx.x == 65) { hb[2] = br[0]; hb[3] = br[1]; hb[4] = br[2]; hb[5] = br[3]; }
    }
    __syncthreads();

    int k = fscale(m.bsC3);
    int hs = m.hs[k];
    int hin = ((hs - 1) >> 1) - 2, win = hin;  // h3
    int hout = hin - 2, wout = win - 2;        // h4
    int WG = (wout + 1) >> 1;
    int idx = (blockIdx.x - m.bsC3[k]) * blockDim.x + threadIdx.x;
    if (idx >= BATCH * hout * WG) return;
    int xg = idx % WG;
    int t2 = idx / WG;
    int y  = t2 % hout;
    int b  = t2 / hout;
    int x0 = xg * 2;

    float acc[2][32];
#pragma unroll
    for (int t = 0; t < 2; t++)
#pragma unroll
        for (int oc = 0; oc < 32; oc++) acc[t][oc] = cb_[oc];

    const float* base = g_c2 + m.offC[k] + (size_t)(b * hin + y) * win * 16;
#pragma unroll
    for (int ky = 0; ky < 3; ky++) {
        const float* rowp = base + (size_t)ky * win * 16;
        for (int ic = 0; ic < 16; ic++) {
            float v[4];
#pragma unroll
            for (int t = 0; t < 4; t++) {
                int xx = x0 + t; if (xx > win - 1) xx = win - 1;
                v[t] = __ldg(rowp + (size_t)xx * 16 + ic);
            }
#pragma unroll
            for (int kx = 0; kx < 3; kx++) {
                const float4* wq = (const float4*)(ws_ + ((ky * 3 + kx) * 16 + ic) * 32);
#pragma unroll
                for (int o4 = 0; o4 < 8; o4++) {
                    float4 wv = wq[o4];
#pragma unroll
                    for (int t = 0; t < 2; t++) {
                        acc[t][o4*4+0] = fmaf(v[t + kx], wv.x, acc[t][o4*4+0]);
                        acc[t][o4*4+1] = fmaf(v[t + kx], wv.y, acc[t][o4*4+1]);
                        acc[t][o4*4+2] = fmaf(v[t + kx], wv.z, acc[t][o4*4+2]);
                        acc[t][o4*4+3] = fmaf(v[t + kx], wv.w, acc[t][o4*4+3]);
                    }
                }
            }
        }
    }

    int ntot = m.ntot;
    float scale = m.scl[k];
    int nbase = m.noff[k] + y * wout;
    float fy = (float)y;

#pragma unroll
    for (int t = 0; t < 2; t++) {
        int x = x0 + t;
        if (x >= wout) continue;

        float z0 = hb[0], z1 = hb[1];
        float r0 = hb[2], r1 = hb[3], r2 = hb[4], r3 = hb[5];
#pragma unroll
        for (int i = 0; i < 32; i++) {
            float z = acc[t][i];
            float vi = z > 0.f ? z : 0.3f * z;   // lrelu
            z0 = fmaf(vi, hwp[i * 2 + 0], z0);
            z1 = fmaf(vi, hwp[i * 2 + 1], z1);
            r0 = fmaf(vi, hwr[i * 4 + 0], r0);
            r1 = fmaf(vi, hwr[i * 4 + 1], r1);
            r2 = fmaf(vi, hwr[i * 4 + 2], r2);
            r3 = fmaf(vi, hwr[i * 4 + 3], r3);
        }
        float score = 1.f / (1.f + expf(z0 - z1));

        int n = nbase + x;
        float fx = (float)x;
        float ulr = rintf((fy * 2.f + 1.f)  / scale);
        float ulc = rintf((fx * 2.f + 1.f)  / scale);
        float drr = rintf((fy * 2.f + 12.f) / scale);
        float drc = rintf((fx * 2.f + 12.f) / scale);

        float* pb = out + ((size_t)b * ntot + n) * 5;
        pb[0] = ulr; pb[1] = ulc; pb[2] = drr; pb[3] = drc; pb[4] = score;

        float* prg = out + (size_t)BATCH * ntot * 5 + ((size_t)b * ntot + n) * 4;
        prg[0] = r0; prg[1] = r1; prg[2] = r2; prg[3] = r3;

        out[(size_t)BATCH * ntot * 9 + (size_t)b * ntot + n] = (score >= 0.6f) ? 1.f : 0.f;
    }
}

// ---------------------------------------------------------------------------
extern "C" void kernel_launch(void* const* d_in, const int* in_sizes, int n_in,
                              void* d_out, int out_size)
{
    const float* inp = (const float*)d_in[0];
    const float* w1  = (const float*)d_in[1];
    const float* b1  = (const float*)d_in[2];
    const float* w2  = (const float*)d_in[3];
    const float* b2  = (const float*)d_in[4];
    const float* w3  = (const float*)d_in[5];
    const float* b3  = (const float*)d_in[6];
    const float* wp  = (const float*)d_in[7];
    const float* bp  = (const float*)d_in[8];
    const float* wr  = (const float*)d_in[9];
    const float* br  = (const float*)d_in[10];
    float* out = (float*)d_out;
    (void)in_sizes; (void)n_in; (void)out_size;

    Meta m;
    int ns = 0;
    {
        double s = 12.0 / 20.0, mm = s * 1080.0;
        while (mm >= 12.0 && ns < NS) {
            m.hs[ns]  = (int)ceil(1080.0 * s);
            m.inv[ns] = (float)(1080.0 / (double)m.hs[ns]);
            m.scl[ns] = (float)s;
            ns++;
            s *= 0.709; mm *= 0.709;
        }
    }

    int oT = 0, oI = 0, oP = 0, oC = 0, ntot = 0;
    m.bsRH[0] = m.bsRV[0] = m.bsCP[0] = m.bsC2[0] = m.bsC3[0] = 0;
    for (int k = 0; k < ns; k++) {
        int hs = m.hs[k], ws = hs;
        int h1 = hs - 2;
        int h2 = (h1 + 1) / 2, w2d = h2;
        int h3 = h2 - 2, w3d = h3;
        int h4 = h3 - 2, w4 = h4;

        m.offT[k] = oT;  oT += BATCH * HIN * ws * 3;
        m.offI[k] = oI;  oI += BATCH * hs * ws * 3;
        m.offP[k] = oP;  oP += BATCH * h2 * w2d * 10;
        m.offC[k] = oC;  oC += BATCH * h3 * w3d * 16;
        m.noff[k] = ntot; ntot += h4 * w4;

        int T;
        T = BATCH * HIN * ws;             m.bsRH[k+1] = m.bsRH[k] + (T + 255) / 256;
        T = BATCH * hs * ws;              m.bsRV[k+1] = m.bsRV[k] + (T + 255) / 256;
        T = BATCH * h2 * w2d;             m.bsCP[k+1] = m.bsCP[k] + (T + 127) / 128;
        T = BATCH * h3 * ((w2d - 2 + 3) / 4); m.bsC2[k+1] = m.bsC2[k] + (T + 127) / 128;
        T = BATCH * h4 * ((w4 + 1) / 2);  m.bsC3[k+1] = m.bsC3[k] + (T + 127) / 128;
    }
    m.ntot = ntot;
    for (int k = ns; k < NS; k++) {       // pad (ns==12 for these constants)
        m.hs[k] = m.hs[ns-1]; m.inv[k] = m.inv[ns-1]; m.scl[k] = m.scl[ns-1];
        m.offT[k] = m.offI[k] = m.offP[k] = m.offC[k] = 0; m.noff[k] = 0;
        m.bsRH[k+1] = m.bsRH[k]; m.bsRV[k+1] = m.bsRV[k];
        m.bsCP[k+1] = m.bsCP[k]; m.bsC2[k+1] = m.bsC2[k]; m.bsC3[k+1] = m.bsC3[k];
        // make fscale never pick padded scales
        m.bsRH[k] = 0x7fffffff; m.bsRV[k] = 0x7fffffff; m.bsCP[k] = 0x7fffffff;
        m.bsC2[k] = 0x7fffffff; m.bsC3[k] = 0x7fffffff;
    }

    k_resize_h <<<m.bsRH[ns], 256>>>(inp, m);
    k_resize_v <<<m.bsRV[ns], 256>>>(m);
    k_conv1pool<<<m.bsCP[ns], 128>>>(w1, b1, m);
    k_conv2    <<<m.bsC2[ns], 128>>>(w2, b2, m);
    k_conv3head<<<m.bsC3[ns], 128>>>(w3, b3, wp, bp, wr, br, out, m);
}

// round 7
// speedup vs baseline: 2.9877x; 1.3612x over previous
#include <cuda_runtime.h>
#include <math.h>

// ---------------------------------------------------------------------------
// MTCNN P-net pyramid, B=4, 1080x1080x3, 12 scales.  R6:
//  - planar (CHW) intermediates -> lane-contiguous conv input loads
//  - packed fma.rn.f32x2 in all conv/head loops (2x fp32 FMA throughput)
//  - resize: reciprocal instead of per-tap FDIV
// Stages (5 mega-kernels, each covers all scales):
//   resize_h | resize_v(+norm, planar out) | conv1+pool | conv2 | conv3+heads
// ---------------------------------------------------------------------------

#define BATCH 4
#define HIN 1080
#define NS 12

typedef unsigned long long u64;

__device__ __forceinline__ u64 pack2(float x) {
    u64 r; asm("mov.b64 %0, {%1, %1};" : "=l"(r) : "f"(x)); return r;
}
__device__ __forceinline__ u64 pk2(float lo, float hi) {
    u64 r; asm("mov.b64 %0, {%1, %2};" : "=l"(r) : "f"(lo), "f"(hi)); return r;
}
__device__ __forceinline__ void unpk(u64 v, float& lo, float& hi) {
    asm("mov.b64 {%0, %1}, %2;" : "=f"(lo), "=f"(hi) : "l"(v));
}
__device__ __forceinline__ void ffma2(u64& d, u64 a, u64 b) {
    asm("fma.rn.f32x2 %0, %1, %2, %3;" : "=l"(d) : "l"(a), "l"(b), "l"(d));
}
__device__ __forceinline__ float lrelu(float z) { return z > 0.f ? z : 0.3f * z; }

__device__ float g_tmpH[28460160 + 1024];  // [4,1080,ws,3] interleaved
__device__ float g_img [10145112 + 1024];  // [4,3,hs,ws]  planar
__device__ float g_p1  [ 8377240 + 1024];  // [4,10,h2,w2] planar
__device__ float g_c2  [13127872 + 1024];  // [4,16,h3,w3] planar

struct Meta {
    int   hs[NS];
    float inv[NS], rinv[NS], scl[NS];
    int   offT[NS], offI[NS], offP[NS], offC[NS];
    int   noff[NS];
    int   ntot;
    int   bsRH[NS + 1], bsRV[NS + 1], bsCP[NS + 1], bsC2[NS + 1], bsC3[NS + 1];
};

__device__ __forceinline__ int fscale(const int* bs)
{
    int k = 0;
#pragma unroll
    for (int i = 1; i < NS; i++)
        if ((int)blockIdx.x >= bs[i]) k = i;
    return k;
}

// ---------------------------------------------------------------------------
// Stage 1: horizontal antialiased resize.  in[4,1080,1080,3] -> tmpH[4,1080,ws,3]
// ---------------------------------------------------------------------------
__global__ void k_resize_h(const float* __restrict__ in, Meta m)
{
    int k = fscale(m.bsRH);
    int ws = m.hs[k];
    float inv = m.inv[k], rinv = m.rinv[k];
    int idx = (blockIdx.x - m.bsRH[k]) * blockDim.x + threadIdx.x;
    if (idx >= BATCH * HIN * ws) return;
    int ox = idx % ws;
    int by = idx / ws;
    float sf = (ox + 0.5f) * inv - 0.5f;
    int j0 = (int)ceilf(sf - inv);  if (j0 < 0) j0 = 0;
    int j1 = (int)floorf(sf + inv); if (j1 > HIN - 1) j1 = HIN - 1;
    float a0 = 0.f, a1 = 0.f, a2 = 0.f, wsum = 0.f;
    const float* row = in + (size_t)by * HIN * 3 + (size_t)j0 * 3;
    float fj = (float)j0;
    for (int j = j0; j <= j1; j++) {
        float wv = fmaxf(fmaf(fabsf(sf - fj), -rinv, 1.f), 0.f);
        wsum += wv;
        a0 = fmaf(wv, row[0], a0);
        a1 = fmaf(wv, row[1], a1);
        a2 = fmaf(wv, row[2], a2);
        row += 3; fj += 1.f;
    }
    float s = 1.f / wsum;
    float* o = g_tmpH + m.offT[k] + (size_t)idx * 3;
    o[0] = a0 * s; o[1] = a1 * s; o[2] = a2 * s;
}

// ---------------------------------------------------------------------------
// Stage 2: vertical resize + (x-127.5)/128.  tmpH -> img planar [4,3,hs,ws]
// ---------------------------------------------------------------------------
__global__ void k_resize_v(Meta m)
{
    int k = fscale(m.bsRV);
    int hs = m.hs[k], ws = hs;
    float inv = m.inv[k], rinv = m.rinv[k];
    int idx = (blockIdx.x - m.bsRV[k]) * blockDim.x + threadIdx.x;
    if (idx >= BATCH * hs * ws) return;
    int x  = idx % ws;
    int t  = idx / ws;
    int oy = t % hs;
    int b  = t / hs;
    float sf = (oy + 0.5f) * inv - 0.5f;
    int j0 = (int)ceilf(sf - inv);  if (j0 < 0) j0 = 0;
    int j1 = (int)floorf(sf + inv); if (j1 > HIN - 1) j1 = HIN - 1;
    float a0 = 0.f, a1 = 0.f, a2 = 0.f, wsum = 0.f;
    const float* p = g_tmpH + m.offT[k] + ((size_t)(b * HIN + j0) * ws + x) * 3;
    size_t step = (size_t)ws * 3;
    float fj = (float)j0;
    for (int j = j0; j <= j1; j++) {
        float wv = fmaxf(fmaf(fabsf(sf - fj), -rinv, 1.f), 0.f);
        wsum += wv;
        a0 = fmaf(wv, p[0], a0);
        a1 = fmaf(wv, p[1], a1);
        a2 = fmaf(wv, p[2], a2);
        p += step; fj += 1.f;
    }
    float s = 1.f / wsum;
    size_t plane = (size_t)hs * ws, pix = (size_t)oy * ws + x;
    float* o = g_img + m.offI[k] + (size_t)b * 3 * plane + pix;
    o[0]         = (a0 * s - 127.5f) * (1.f / 128.f);
    o[plane]     = (a1 * s - 127.5f) * (1.f / 128.f);
    o[2 * plane] = (a2 * s - 127.5f) * (1.f / 128.f);
}

// ---------------------------------------------------------------------------
// Stage 3: conv3x3 3->10 + lrelu fused with 2x2/2 maxpool. Planar in/out.
// One thread per pooled pixel; 4 conv pixels in packed-pair registers.
// ---------------------------------------------------------------------------
__global__ void __launch_bounds__(128)
k_conv1pool(const float* __restrict__ w, const float* __restrict__ bias, Meta m)
{
    __shared__ __align__(16) float ws_[272];
    __shared__ __align__(8)  float bs_[10];
    for (int i = threadIdx.x; i < 270; i += blockDim.x) ws_[i] = w[i];
    if (threadIdx.x < 10) bs_[threadIdx.x] = bias[threadIdx.x];
    __syncthreads();

    int k = fscale(m.bsCP);
    int hs = m.hs[k], ws = hs;
    int h1 = hs - 2, w1 = ws - 2;
    int h2 = (h1 + 1) >> 1, w2 = (w1 + 1) >> 1;
    int idx = (blockIdx.x - m.bsCP[k]) * blockDim.x + threadIdx.x;
    if (idx >= BATCH * h2 * w2) return;
    int x = idx % w2;
    int t = idx / w2;
    int y = t % h2;
    int b = t / h2;
    int r0 = 2 * y, c0 = 2 * x;
    bool vr = (r0 + 1 < h1), vc = (c0 + 1 < w1);

    u64 acc[4][5];
    {
        const u64* bq = (const u64*)bs_;
#pragma unroll
        for (int p = 0; p < 4; p++)
#pragma unroll
            for (int q = 0; q < 5; q++) acc[p][q] = bq[q];
    }

    size_t plane = (size_t)hs * ws;
    const float* imgb = g_img + m.offI[k] + (size_t)b * 3 * plane;

#pragma unroll
    for (int ic = 0; ic < 3; ic++) {
        u64 pp[4][4];
#pragma unroll
        for (int i = 0; i < 4; i++) {
            int ry = r0 + i; if (ry > hs - 1) ry = hs - 1;
            const float* rp = imgb + (size_t)ic * plane + (size_t)ry * ws;
#pragma unroll
            for (int j = 0; j < 4; j++) {
                int cx = c0 + j; if (cx > ws - 1) cx = ws - 1;
                pp[i][j] = pack2(__ldg(rp + cx));
            }
        }
#pragma unroll
        for (int ky = 0; ky < 3; ky++)
#pragma unroll
        for (int kx = 0; kx < 3; kx++) {
            const u64* wq = (const u64*)(ws_ + ((ky * 3 + kx) * 3 + ic) * 10);
#pragma unroll
            for (int q = 0; q < 5; q++) {
                u64 wv = wq[q];
                ffma2(acc[0][q], pp[ky][kx],         wv);
                ffma2(acc[1][q], pp[ky][kx + 1],     wv);
                ffma2(acc[2][q], pp[ky + 1][kx],     wv);
                ffma2(acc[3][q], pp[ky + 1][kx + 1], wv);
            }
        }
    }

    size_t oplane = (size_t)h2 * w2;
    float* ob = g_p1 + m.offP[k] + (size_t)b * 10 * oplane + (size_t)y * w2 + x;
#pragma unroll
    for (int q = 0; q < 5; q++) {
        float z0, z1, a0, a1, u0, u1;
        unpk(acc[0][q], z0, z1); a0 = lrelu(z0); a1 = lrelu(z1);
        if (vc) { unpk(acc[1][q], z0, z1); a0 = fmaxf(a0, lrelu(z0)); a1 = fmaxf(a1, lrelu(z1)); }
        if (vr) { unpk(acc[2][q], z0, z1); a0 = fmaxf(a0, lrelu(z0)); a1 = fmaxf(a1, lrelu(z1));
            if (vc) { unpk(acc[3][q], u0, u1); a0 = fmaxf(a0, lrelu(u0)); a1 = fmaxf(a1, lrelu(u1)); } }
        ob[(size_t)(2 * q)     * oplane] = a0;
        ob[(size_t)(2 * q + 1) * oplane] = a1;
    }
}

// ---------------------------------------------------------------------------
// Stage 4: conv3x3 10->16 + lrelu, planar in/out. TX=4.
// ---------------------------------------------------------------------------
__global__ void __launch_bounds__(128)
k_conv2(const float* __restrict__ w, const float* __restrict__ bias, Meta m)
{
    __shared__ __align__(16) float ws_[1440];
    __shared__ __align__(8)  float bs_[16];
    {
        const float4* s4 = (const float4*)w;
        float4* d4 = (float4*)ws_;
        for (int i = threadIdx.x; i < 360; i += blockDim.x) d4[i] = s4[i];
        if (threadIdx.x < 16) bs_[threadIdx.x] = bias[threadIdx.x];
    }
    __syncthreads();

    int k = fscale(m.bsC2);
    int hs = m.hs[k];
    int hin = (hs - 1) >> 1, win = hin;
    int hout = hin - 2, wout = win - 2;
    int WG = (wout + 3) >> 2;
    int idx = (blockIdx.x - m.bsC2[k]) * blockDim.x + threadIdx.x;
    if (idx >= BATCH * hout * WG) return;
    int xg = idx % WG;
    int t2 = idx / WG;
    int y  = t2 % hout;
    int b  = t2 / hout;
    int x0 = xg * 4;

    u64 acc[4][8];
    {
        const u64* bq = (const u64*)bs_;
#pragma unroll
        for (int t = 0; t < 4; t++)
#pragma unroll
            for (int q = 0; q < 8; q++) acc[t][q] = bq[q];
    }

    size_t plane = (size_t)hin * win;
    const float* pb = g_p1 + m.offP[k] + (size_t)b * 10 * plane;

#pragma unroll
    for (int ky = 0; ky < 3; ky++) {
        for (int ic = 0; ic < 10; ic++) {
            const float* rowp = pb + (size_t)ic * plane + (size_t)(y + ky) * win;
            u64 vv[6];
#pragma unroll
            for (int t = 0; t < 6; t++) {
                int xx = x0 + t; if (xx > win - 1) xx = win - 1;
                vv[t] = pack2(__ldg(rowp + xx));
            }
#pragma unroll
            for (int kx = 0; kx < 3; kx++) {
                const u64* wq = (const u64*)(ws_ + ((ky * 3 + kx) * 10 + ic) * 16);
#pragma unroll
                for (int q = 0; q < 8; q++) {
                    u64 wv = wq[q];
#pragma unroll
                    for (int t = 0; t < 4; t++)
                        ffma2(acc[t][q], vv[t + kx], wv);
                }
            }
        }
    }

    size_t oplane = (size_t)hout * wout;
    float* ob = g_c2 + m.offC[k] + (size_t)b * 16 * oplane + (size_t)y * wout;
#pragma unroll
    for (int t = 0; t < 4; t++) {
        int x = x0 + t;
        if (x < wout) {
#pragma unroll
            for (int q = 0; q < 8; q++) {
                float z0, z1;
                unpk(acc[t][q], z0, z1);
                ob[(size_t)(2 * q)     * oplane + x] = lrelu(z0);
                ob[(size_t)(2 * q + 1) * oplane + x] = lrelu(z1);
            }
        }
    }
}

// ---------------------------------------------------------------------------
// Stage 5: conv3x3 16->32 + lrelu fused with heads + boxes + mask. TX=2.
// Output layout: boxes[4][N][5] | reg[4][N][4] | mask[4][N]
// ---------------------------------------------------------------------------
__global__ void __launch_bounds__(128)
k_conv3head(const float* __restrict__ w, const float* __restrict__ bias,
            const float* __restrict__ wp, const float* __restrict__ bp,
            const float* __restrict__ wr, const float* __restrict__ br,
            float* __restrict__ out, Meta m)
{
    __shared__ __align__(16) float ws_[4608];
    __shared__ __align__(8)  float cb_[32], hwp[64], hwr[128], hb[6];
    {
        const float4* s4 = (const float4*)w;
        float4* d4 = (float4*)ws_;
        for (int i = threadIdx.x; i < 1152; i += blockDim.x) d4[i] = s4[i];
        if (threadIdx.x < 32) cb_[threadIdx.x] = bias[threadIdx.x];
        if (threadIdx.x < 64) hwp[threadIdx.x] = wp[threadIdx.x];
        hwr[threadIdx.x] = wr[threadIdx.x];
        if (threadIdx.x == 64) { hb[0] = bp[0]; hb[1] = bp[1]; }
        if (threadIdx.x == 65) { hb[2] = br[0]; hb[3] = br[1]; hb[4] = br[2]; hb[5] = br[3]; }
    }
    __syncthreads();

    int k = fscale(m.bsC3);
    int hs = m.hs[k];
    int hin = ((hs - 1) >> 1) - 2, win = hin;
    int hout = hin - 2, wout = win - 2;
    int WG = (wout + 1) >> 1;
    int idx = (blockIdx.x - m.bsC3[k]) * blockDim.x + threadIdx.x;
    if (idx >= BATCH * hout * WG) return;
    int xg = idx % WG;
    int t2 = idx / WG;
    int y  = t2 % hout;
    int b  = t2 / hout;
    int x0 = xg * 2;

    u64 acc[2][16];
    {
        const u64* bq = (const u64*)cb_;
#pragma unroll
        for (int t = 0; t < 2; t++)
#pragma unroll
            for (int q = 0; q < 16; q++) acc[t][q] = bq[q];
    }

    size_t plane = (size_t)hin * win;
    const float* cb = g_c2 + m.offC[k] + (size_t)b * 16 * plane;

#pragma unroll
    for (int ky = 0; ky < 3; ky++) {
        for (int ic = 0; ic < 16; ic++) {
            const float* rowp = cb + (size_t)ic * plane + (size_t)(y + ky) * win;
            u64 vv[4];
#pragma unroll
            for (int t = 0; t < 4; t++) {
                int xx = x0 + t; if (xx > win - 1) xx = win - 1;
                vv[t] = pack2(__ldg(rowp + xx));
            }
#pragma unroll
            for (int kx = 0; kx < 3; kx++) {
                const u64* wq = (const u64*)(ws_ + ((ky * 3 + kx) * 16 + ic) * 32);
#pragma unroll
                for (int q = 0; q < 16; q++) {
                    u64 wv = wq[q];
                    ffma2(acc[0][q], vv[kx],     wv);
                    ffma2(acc[1][q], vv[kx + 1], wv);
                }
            }
        }
    }

    int ntot = m.ntot;
    float scale = m.scl[k];
    int nbase = m.noff[k] + y * wout;
    float fy = (float)y;
    const u64* wp64  = (const u64*)hwp;
    const u64* wr64  = (const u64*)hwr;

#pragma unroll
    for (int t = 0; t < 2; t++) {
        int x = x0 + t;
        if (x >= wout) continue;

        u64 zz = pk2(hb[0], hb[1]);
        u64 rA = pk2(hb[2], hb[3]);
        u64 rB = pk2(hb[4], hb[5]);
#pragma unroll
        for (int q = 0; q < 16; q++) {
            float z0, z1;
            unpk(acc[t][q], z0, z1);
            u64 v0 = pack2(lrelu(z0));
            u64 v1 = pack2(lrelu(z1));
            int c0 = 2 * q, c1 = 2 * q + 1;
            ffma2(zz, v0, wp64[c0]);     ffma2(zz, v1, wp64[c1]);
            ffma2(rA, v0, wr64[2 * c0]); ffma2(rA, v1, wr64[2 * c1]);
            ffma2(rB, v0, wr64[2 * c0 + 1]); ffma2(rB, v1, wr64[2 * c1 + 1]);
        }
        float z0, z1, r0, r1, r2, r3;
        unpk(zz, z0, z1);
        unpk(rA, r0, r1);
        unpk(rB, r2, r3);
        float score = 1.f / (1.f + expf(z0 - z1));

        int n = nbase + x;
        float fx = (float)x;
        float ulr = rintf((fy * 2.f + 1.f)  / scale);
        float ulc = rintf((fx * 2.f + 1.f)  / scale);
        float drr = rintf((fy * 2.f + 12.f) / scale);
        float drc = rintf((fx * 2.f + 12.f) / scale);

        float* pbx = out + ((size_t)b * ntot + n) * 5;
        pbx[0] = ulr; pbx[1] = ulc; pbx[2] = drr; pbx[3] = drc; pbx[4] = score;

        float* prg = out + (size_t)BATCH * ntot * 5 + ((size_t)b * ntot + n) * 4;
        prg[0] = r0; prg[1] = r1; prg[2] = r2; prg[3] = r3;

        out[(size_t)BATCH * ntot * 9 + (size_t)b * ntot + n] = (score >= 0.6f) ? 1.f : 0.f;
    }
}

// ---------------------------------------------------------------------------
extern "C" void kernel_launch(void* const* d_in, const int* in_sizes, int n_in,
                              void* d_out, int out_size)
{
    const float* inp = (const float*)d_in[0];
    const float* w1  = (const float*)d_in[1];
    const float* b1  = (const float*)d_in[2];
    const float* w2  = (const float*)d_in[3];
    const float* b2  = (const float*)d_in[4];
    const float* w3  = (const float*)d_in[5];
    const float* b3  = (const float*)d_in[6];
    const float* wp  = (const float*)d_in[7];
    const float* bp  = (const float*)d_in[8];
    const float* wr  = (const float*)d_in[9];
    const float* br  = (const float*)d_in[10];
    float* out = (float*)d_out;
    (void)in_sizes; (void)n_in; (void)out_size;

    Meta m;
    int ns = 0;
    {
        double s = 12.0 / 20.0, mm = s * 1080.0;
        while (mm >= 12.0 && ns < NS) {
            m.hs[ns]   = (int)ceil(1080.0 * s);
            m.inv[ns]  = (float)(1080.0 / (double)m.hs[ns]);
            m.rinv[ns] = (float)((double)m.hs[ns] / 1080.0);
            m.scl[ns]  = (float)s;
            ns++;
            s *= 0.709; mm *= 0.709;
        }
    }

    int oT = 0, oI = 0, oP = 0, oC = 0, ntot = 0;
    m.bsRH[0] = m.bsRV[0] = m.bsCP[0] = m.bsC2[0] = m.bsC3[0] = 0;
    for (int k = 0; k < ns; k++) {
        int hs = m.hs[k], ws = hs;
        int h1 = hs - 2;
        int h2 = (h1 + 1) / 2, w2d = h2;
        int h3 = h2 - 2, w3d = h3;
        int h4 = h3 - 2, w4 = h4;

        m.offT[k] = oT;  oT += BATCH * HIN * ws * 3;
        m.offI[k] = oI;  oI += BATCH * hs * ws * 3;
        m.offP[k] = oP;  oP += BATCH * h2 * w2d * 10;
        m.offC[k] = oC;  oC += BATCH * h3 * w3d * 16;
        m.noff[k] = ntot; ntot += h4 * w4;

        int T;
        T = BATCH * HIN * ws;                 m.bsRH[k+1] = m.bsRH[k] + (T + 255) / 256;
        T = BATCH * hs * ws;                  m.bsRV[k+1] = m.bsRV[k] + (T + 255) / 256;
        T = BATCH * h2 * w2d;                 m.bsCP[k+1] = m.bsCP[k] + (T + 127) / 128;
        T = BATCH * h3 * ((w2d - 2 + 3) / 4); m.bsC2[k+1] = m.bsC2[k] + (T + 127) / 128;
        T = BATCH * h4 * ((w4 + 1) / 2);      m.bsC3[k+1] = m.bsC3[k] + (T + 127) / 128;
    }
    m.ntot = ntot;
    for (int k = ns; k < NS; k++) {
        m.hs[k] = m.hs[ns-1]; m.inv[k] = m.inv[ns-1];
        m.rinv[k] = m.rinv[ns-1]; m.scl[k] = m.scl[ns-1];
        m.offT[k] = m.offI[k] = m.offP[k] = m.offC[k] = 0; m.noff[k] = 0;
        m.bsRH[k+1] = m.bsRH[k]; m.bsRV[k+1] = m.bsRV[k];
        m.bsCP[k+1] = m.bsCP[k]; m.bsC2[k+1] = m.bsC2[k]; m.bsC3[k+1] = m.bsC3[k];
        m.bsRH[k] = 0x7fffffff; m.bsRV[k] = 0x7fffffff; m.bsCP[k] = 0x7fffffff;
        m.bsC2[k] = 0x7fffffff; m.bsC3[k] = 0x7fffffff;
    }

    k_resize_h <<<m.bsRH[ns], 256>>>(inp, m);
    k_resize_v <<<m.bsRV[ns], 256>>>(m);
    k_conv1pool<<<m.bsCP[ns], 128>>>(w1, b1, m);
    k_conv2    <<<m.bsC2[ns], 128>>>(w2, b2, m);
    k_conv3head<<<m.bsC3[ns], 128>>>(w3, b3, wp, bp, wr, br, out, m);
}

// round 8
// speedup vs baseline: 3.2328x; 1.0820x over previous
#include <cuda_runtime.h>
#include <math.h>

// ---------------------------------------------------------------------------
// MTCNN P-net pyramid, B=4, 1080x1080x3, 12 scales.  R7:
//  - LDS.128 weight loads (ulonglong2) in all convs
//  - int32 indexing, __launch_bounds__(128,4) -> 4 blocks/SM
//  - double-buffered input prefetch in conv2/conv3head
// Stages: resize_h | resize_v | conv1+pool | conv2 | conv3+heads
// ---------------------------------------------------------------------------

#define BATCH 4
#define HIN 1080
#define NS 12

typedef unsigned long long u64;

__device__ __forceinline__ u64 pack2(float x) {
    u64 r; asm("mov.b64 %0, {%1, %1};" : "=l"(r) : "f"(x)); return r;
}
__device__ __forceinline__ u64 pk2(float lo, float hi) {
    u64 r; asm("mov.b64 %0, {%1, %2};" : "=l"(r) : "f"(lo), "f"(hi)); return r;
}
__device__ __forceinline__ void unpk(u64 v, float& lo, float& hi) {
    asm("mov.b64 {%0, %1}, %2;" : "=f"(lo), "=f"(hi) : "l"(v));
}
__device__ __forceinline__ void ffma2(u64& d, u64 a, u64 b) {
    asm("fma.rn.f32x2 %0, %1, %2, %3;" : "=l"(d) : "l"(a), "l"(b), "l"(d));
}
__device__ __forceinline__ float lrelu(float z) { return z > 0.f ? z : 0.3f * z; }

__device__ float g_tmpH[28460160 + 1024];  // [4,1080,ws,3] interleaved
__device__ float g_img [10145112 + 1024];  // [4,3,hs,ws]  planar
__device__ float g_p1  [ 8377240 + 1024];  // [4,10,h2,w2] planar
__device__ float g_c2  [13127872 + 1024];  // [4,16,h3,w3] planar

struct Meta {
    int   hs[NS];
    float inv[NS], rinv[NS], scl[NS];
    int   offT[NS], offI[NS], offP[NS], offC[NS];
    int   noff[NS];
    int   ntot;
    int   bsRH[NS + 1], bsRV[NS + 1], bsCP[NS + 1], bsC2[NS + 1], bsC3[NS + 1];
};

__device__ __forceinline__ int fscale(const int* bs)
{
    int k = 0;
#pragma unroll
    for (int i = 1; i < NS; i++)
        if ((int)blockIdx.x >= bs[i]) k = i;
    return k;
}

// ---------------------------------------------------------------------------
// Stage 1: horizontal antialiased resize.  in[4,1080,1080,3] -> tmpH[4,1080,ws,3]
// ---------------------------------------------------------------------------
__global__ void k_resize_h(const float* __restrict__ in, Meta m)
{
    int k = fscale(m.bsRH);
    int ws = m.hs[k];
    float inv = m.inv[k], rinv = m.rinv[k];
    int idx = (blockIdx.x - m.bsRH[k]) * blockDim.x + threadIdx.x;
    if (idx >= BATCH * HIN * ws) return;
    int ox = idx % ws;
    int by = idx / ws;
    float sf = (ox + 0.5f) * inv - 0.5f;
    int j0 = (int)ceilf(sf - inv);  if (j0 < 0) j0 = 0;
    int j1 = (int)floorf(sf + inv); if (j1 > HIN - 1) j1 = HIN - 1;
    float a0 = 0.f, a1 = 0.f, a2 = 0.f, wsum = 0.f;
    const float* row = in + by * (HIN * 3) + j0 * 3;
    float fj = (float)j0;
    for (int j = j0; j <= j1; j++) {
        float wv = fmaxf(fmaf(fabsf(sf - fj), -rinv, 1.f), 0.f);
        wsum += wv;
        a0 = fmaf(wv, row[0], a0);
        a1 = fmaf(wv, row[1], a1);
        a2 = fmaf(wv, row[2], a2);
        row += 3; fj += 1.f;
    }
    float s = 1.f / wsum;
    float* o = g_tmpH + m.offT[k] + idx * 3;
    o[0] = a0 * s; o[1] = a1 * s; o[2] = a2 * s;
}

// ---------------------------------------------------------------------------
// Stage 2: vertical resize + (x-127.5)/128.  tmpH -> img planar [4,3,hs,ws]
// ---------------------------------------------------------------------------
__global__ void k_resize_v(Meta m)
{
    int k = fscale(m.bsRV);
    int hs = m.hs[k], ws = hs;
    float inv = m.inv[k], rinv = m.rinv[k];
    int idx = (blockIdx.x - m.bsRV[k]) * blockDim.x + threadIdx.x;
    if (idx >= BATCH * hs * ws) return;
    int x  = idx % ws;
    int t  = idx / ws;
    int oy = t % hs;
    int b  = t / hs;
    float sf = (oy + 0.5f) * inv - 0.5f;
    int j0 = (int)ceilf(sf - inv);  if (j0 < 0) j0 = 0;
    int j1 = (int)floorf(sf + inv); if (j1 > HIN - 1) j1 = HIN - 1;
    float a0 = 0.f, a1 = 0.f, a2 = 0.f, wsum = 0.f;
    const float* p = g_tmpH + m.offT[k] + ((b * HIN + j0) * ws + x) * 3;
    int step = ws * 3;
    float fj = (float)j0;
    for (int j = j0; j <= j1; j++) {
        float wv = fmaxf(fmaf(fabsf(sf - fj), -rinv, 1.f), 0.f);
        wsum += wv;
        a0 = fmaf(wv, p[0], a0);
        a1 = fmaf(wv, p[1], a1);
        a2 = fmaf(wv, p[2], a2);
        p += step; fj += 1.f;
    }
    float s = 1.f / wsum;
    int plane = hs * ws, pix = oy * ws + x;
    float* o = g_img + m.offI[k] + b * 3 * plane + pix;
    o[0]         = (a0 * s - 127.5f) * (1.f / 128.f);
    o[plane]     = (a1 * s - 127.5f) * (1.f / 128.f);
    o[2 * plane] = (a2 * s - 127.5f) * (1.f / 128.f);
}

// ---------------------------------------------------------------------------
// Stage 3: conv3x3 3->10 + lrelu fused with 2x2/2 maxpool. Planar in/out.
// Weights padded to 12 floats per (ky,kx,ic) tap -> LDS.128-friendly.
// ---------------------------------------------------------------------------
__global__ void __launch_bounds__(128, 4)
k_conv1pool(const float* __restrict__ w, const float* __restrict__ bias, Meta m)
{
    __shared__ __align__(16) float ws_[27 * 12];
    __shared__ __align__(8)  float bs_[10];
    for (int i = threadIdx.x; i < 270; i += blockDim.x) {
        int e = i / 10, p = i - e * 10;
        ws_[e * 12 + p] = w[i];
    }
    if (threadIdx.x < 10) bs_[threadIdx.x] = bias[threadIdx.x];
    __syncthreads();

    int k = fscale(m.bsCP);
    int hs = m.hs[k], ws = hs;
    int h1 = hs - 2, w1 = ws - 2;
    int h2 = (h1 + 1) >> 1, w2 = (w1 + 1) >> 1;
    int idx = (blockIdx.x - m.bsCP[k]) * blockDim.x + threadIdx.x;
    if (idx >= BATCH * h2 * w2) return;
    int x = idx % w2;
    int t = idx / w2;
    int y = t % h2;
    int b = t / h2;
    int r0 = 2 * y, c0 = 2 * x;
    bool vr = (r0 + 1 < h1), vc = (c0 + 1 < w1);

    u64 acc[4][5];
    {
        const u64* bq = (const u64*)bs_;
#pragma unroll
        for (int p = 0; p < 4; p++) {
            u64 b0 = bq[0], b1 = bq[1], b2 = bq[2], b3 = bq[3], b4 = bq[4];
            acc[p][0] = b0; acc[p][1] = b1; acc[p][2] = b2; acc[p][3] = b3; acc[p][4] = b4;
        }
    }

    int plane = hs * ws;
    const float* imgb = g_img + m.offI[k] + b * 3 * plane;

#pragma unroll
    for (int ic = 0; ic < 3; ic++) {
        u64 pp[4][4];
#pragma unroll
        for (int i = 0; i < 4; i++) {
            int ry = r0 + i; if (ry > hs - 1) ry = hs - 1;
            const float* rp = imgb + ic * plane + ry * ws;
#pragma unroll
            for (int j = 0; j < 4; j++) {
                int cx = c0 + j; if (cx > ws - 1) cx = ws - 1;
                pp[i][j] = pack2(__ldg(rp + cx));
            }
        }
#pragma unroll
        for (int ky = 0; ky < 3; ky++)
#pragma unroll
        for (int kx = 0; kx < 3; kx++) {
            const float* wbase = ws_ + ((ky * 3 + kx) * 3 + ic) * 12;
            ulonglong2 w01 = *(const ulonglong2*)wbase;        // oc pairs 0,1
            ulonglong2 w23 = *(const ulonglong2*)(wbase + 4);  // oc pairs 2,3
            u64        w4  = *(const u64*)(wbase + 8);         // oc pair 4
            u64 wv[5] = { w01.x, w01.y, w23.x, w23.y, w4 };
#pragma unroll
            for (int q = 0; q < 5; q++) {
                ffma2(acc[0][q], pp[ky][kx],         wv[q]);
                ffma2(acc[1][q], pp[ky][kx + 1],     wv[q]);
                ffma2(acc[2][q], pp[ky + 1][kx],     wv[q]);
                ffma2(acc[3][q], pp[ky + 1][kx + 1], wv[q]);
            }
        }
    }

    int oplane = h2 * w2;
    float* ob = g_p1 + m.offP[k] + b * 10 * oplane + y * w2 + x;
#pragma unroll
    for (int q = 0; q < 5; q++) {
        float z0, z1, a0, a1, u0, u1;
        unpk(acc[0][q], z0, z1); a0 = lrelu(z0); a1 = lrelu(z1);
        if (vc) { unpk(acc[1][q], z0, z1); a0 = fmaxf(a0, lrelu(z0)); a1 = fmaxf(a1, lrelu(z1)); }
        if (vr) { unpk(acc[2][q], z0, z1); a0 = fmaxf(a0, lrelu(z0)); a1 = fmaxf(a1, lrelu(z1));
            if (vc) { unpk(acc[3][q], u0, u1); a0 = fmaxf(a0, lrelu(u0)); a1 = fmaxf(a1, lrelu(u1)); } }
        ob[(2 * q)     * oplane] = a0;
        ob[(2 * q + 1) * oplane] = a1;
    }
}

// ---------------------------------------------------------------------------
// Stage 4: conv3x3 10->16 + lrelu, planar in/out. TX=4. Double-buffered input.
// ---------------------------------------------------------------------------
__global__ void __launch_bounds__(128, 4)
k_conv2(const float* __restrict__ w, const float* __restrict__ bias, Meta m)
{
    __shared__ __align__(16) float ws_[1440];
    __shared__ __align__(8)  float bs_[16];
    {
        const float4* s4 = (const float4*)w;
        float4* d4 = (float4*)ws_;
        for (int i = threadIdx.x; i < 360; i += blockDim.x) d4[i] = s4[i];
        if (threadIdx.x < 16) bs_[threadIdx.x] = bias[threadIdx.x];
    }
    __syncthreads();

    int k = fscale(m.bsC2);
    int hs = m.hs[k];
    int hin = (hs - 1) >> 1, win = hin;
    int hout = hin - 2, wout = win - 2;
    int WG = (wout + 3) >> 2;
    int idx = (blockIdx.x - m.bsC2[k]) * blockDim.x + threadIdx.x;
    if (idx >= BATCH * hout * WG) return;
    int xg = idx % WG;
    int t2 = idx / WG;
    int y  = t2 % hout;
    int b  = t2 / hout;
    int x0 = xg * 4;

    u64 acc[4][8];
    {
        const u64* bq = (const u64*)bs_;
#pragma unroll
        for (int q = 0; q < 8; q++) {
            u64 bv = bq[q];
            acc[0][q] = bv; acc[1][q] = bv; acc[2][q] = bv; acc[3][q] = bv;
        }
    }

    int plane = hin * win;
    const float* pb = g_p1 + m.offP[k] + b * 10 * plane;
    int xc[6];
#pragma unroll
    for (int t = 0; t < 6; t++) { int xx = x0 + t; xc[t] = xx > win - 1 ? win - 1 : xx; }

#pragma unroll
    for (int ky = 0; ky < 3; ky++) {
        const float* rbase = pb + (y + ky) * win;
        u64 vbuf[2][6];
#pragma unroll
        for (int t = 0; t < 6; t++) vbuf[0][t] = pack2(__ldg(rbase + xc[t]));

#pragma unroll 2
        for (int ic = 0; ic < 10; ic++) {
            int cur = ic & 1;
            if (ic < 9) {
                const float* rn = rbase + (ic + 1) * plane;
#pragma unroll
                for (int t = 0; t < 6; t++) vbuf[cur ^ 1][t] = pack2(__ldg(rn + xc[t]));
            }
#pragma unroll
            for (int kx = 0; kx < 3; kx++) {
                const ulonglong2* wq = (const ulonglong2*)(ws_ + ((ky * 3 + kx) * 10 + ic) * 16);
#pragma unroll
                for (int q2 = 0; q2 < 4; q2++) {
                    ulonglong2 wv = wq[q2];
#pragma unroll
                    for (int t = 0; t < 4; t++) {
                        ffma2(acc[t][2 * q2 + 0], vbuf[cur][t + kx], wv.x);
                        ffma2(acc[t][2 * q2 + 1], vbuf[cur][t + kx], wv.y);
                    }
                }
            }
        }
    }

    int oplane = hout * wout;
    float* ob = g_c2 + m.offC[k] + b * 16 * oplane + y * wout;
#pragma unroll
    for (int t = 0; t < 4; t++) {
        int x = x0 + t;
        if (x < wout) {
#pragma unroll
            for (int q = 0; q < 8; q++) {
                float z0, z1;
                unpk(acc[t][q], z0, z1);
                ob[(2 * q)     * oplane + x] = lrelu(z0);
                ob[(2 * q + 1) * oplane + x] = lrelu(z1);
            }
        }
    }
}

// ---------------------------------------------------------------------------
// Stage 5: conv3x3 16->32 + lrelu fused with heads + boxes + mask. TX=2.
// Output layout: boxes[4][N][5] | reg[4][N][4] | mask[4][N]
// ---------------------------------------------------------------------------
__global__ void __launch_bounds__(128, 4)
k_conv3head(const float* __restrict__ w, const float* __restrict__ bias,
            const float* __restrict__ wp, const float* __restrict__ bp,
            const float* __restrict__ wr, const float* __restrict__ br,
            float* __restrict__ out, Meta m)
{
    __shared__ __align__(16) float ws_[4608];
    __shared__ __align__(8)  float cb_[32], hwp[64], hwr[128], hb[6];
    {
        const float4* s4 = (const float4*)w;
        float4* d4 = (float4*)ws_;
        for (int i = threadIdx.x; i < 1152; i += blockDim.x) d4[i] = s4[i];
        if (threadIdx.x < 32) cb_[threadIdx.x] = bias[threadIdx.x];
        if (threadIdx.x < 64) hwp[threadIdx.x] = wp[threadIdx.x];
        hwr[threadIdx.x] = wr[threadIdx.x];
        if (threadIdx.x == 64) { hb[0] = bp[0]; hb[1] = bp[1]; }
        if (threadIdx.x == 65) { hb[2] = br[0]; hb[3] = br[1]; hb[4] = br[2]; hb[5] = br[3]; }
    }
    __syncthreads();

    int k = fscale(m.bsC3);
    int hs = m.hs[k];
    int hin = ((hs - 1) >> 1) - 2, win = hin;
    int hout = hin - 2, wout = win - 2;
    int WG = (wout + 1) >> 1;
    int idx = (blockIdx.x - m.bsC3[k]) * blockDim.x + threadIdx.x;
    if (idx >= BATCH * hout * WG) return;
    int xg = idx % WG;
    int t2 = idx / WG;
    int y  = t2 % hout;
    int b  = t2 / hout;
    int x0 = xg * 2;

    u64 acc[2][16];
    {
        const u64* bq = (const u64*)cb_;
#pragma unroll
        for (int q = 0; q < 16; q++) {
            u64 bv = bq[q];
            acc[0][q] = bv; acc[1][q] = bv;
        }
    }

    int plane = hin * win;
    const float* cb = g_c2 + m.offC[k] + b * 16 * plane;
    int xc[4];
#pragma unroll
    for (int t = 0; t < 4; t++) { int xx = x0 + t; xc[t] = xx > win - 1 ? win - 1 : xx; }

#pragma unroll
    for (int ky = 0; ky < 3; ky++) {
        const float* rbase = cb + (y + ky) * win;
        u64 vbuf[2][4];
#pragma unroll
        for (int t = 0; t < 4; t++) vbuf[0][t] = pack2(__ldg(rbase + xc[t]));

#pragma unroll 2
        for (int ic = 0; ic < 16; ic++) {
            int cur = ic & 1;
            if (ic < 15) {
                const float* rn = rbase + (ic + 1) * plane;
#pragma unroll
                for (int t = 0; t < 4; t++) vbuf[cur ^ 1][t] = pack2(__ldg(rn + xc[t]));
            }
#pragma unroll
            for (int kx = 0; kx < 3; kx++) {
                const ulonglong2* wq = (const ulonglong2*)(ws_ + ((ky * 3 + kx) * 16 + ic) * 32);
#pragma unroll
                for (int q2 = 0; q2 < 8; q2++) {
                    ulonglong2 wv = wq[q2];
                    ffma2(acc[0][2 * q2 + 0], vbuf[cur][kx],     wv.x);
                    ffma2(acc[0][2 * q2 + 1], vbuf[cur][kx],     wv.y);
                    ffma2(acc[1][2 * q2 + 0], vbuf[cur][kx + 1], wv.x);
                    ffma2(acc[1][2 * q2 + 1], vbuf[cur][kx + 1], wv.y);
                }
            }
        }
    }

    int ntot = m.ntot;
    float scale = m.scl[k];
    int nbase = m.noff[k] + y * wout;
    float fy = (float)y;
    const u64* wp64 = (const u64*)hwp;
    const u64* wr64 = (const u64*)hwr;

#pragma unroll
    for (int t = 0; t < 2; t++) {
        int x = x0 + t;
        if (x >= wout) continue;

        u64 zz = pk2(hb[0], hb[1]);
        u64 rA = pk2(hb[2], hb[3]);
        u64 rB = pk2(hb[4], hb[5]);
#pragma unroll
        for (int q = 0; q < 16; q++) {
            float z0, z1;
            unpk(acc[t][q], z0, z1);
            u64 v0 = pack2(lrelu(z0));
            u64 v1 = pack2(lrelu(z1));
            int c0 = 2 * q, c1 = 2 * q + 1;
            ffma2(zz, v0, wp64[c0]);         ffma2(zz, v1, wp64[c1]);
            ffma2(rA, v0, wr64[2 * c0]);     ffma2(rA, v1, wr64[2 * c1]);
            ffma2(rB, v0, wr64[2 * c0 + 1]); ffma2(rB, v1, wr64[2 * c1 + 1]);
        }
        float z0, z1, r0, r1, r2, r3;
        unpk(zz, z0, z1);
        unpk(rA, r0, r1);
        unpk(rB, r2, r3);
        float score = 1.f / (1.f + expf(z0 - z1));

        int n = nbase + x;
        float fx = (float)x;
        float ulr = rintf((fy * 2.f + 1.f)  / scale);
        float ulc = rintf((fx * 2.f + 1.f)  / scale);
        float drr = rintf((fy * 2.f + 12.f) / scale);
        float drc = rintf((fx * 2.f + 12.f) / scale);

        float* pbx = out + (b * ntot + n) * 5;
        pbx[0] = ulr; pbx[1] = ulc; pbx[2] = drr; pbx[3] = drc; pbx[4] = score;

        float* prg = out + BATCH * ntot * 5 + (b * ntot + n) * 4;
        prg[0] = r0; prg[1] = r1; prg[2] = r2; prg[3] = r3;

        out[BATCH * ntot * 9 + b * ntot + n] = (score >= 0.6f) ? 1.f : 0.f;
    }
}

// ---------------------------------------------------------------------------
extern "C" void kernel_launch(void* const* d_in, const int* in_sizes, int n_in,
                              void* d_out, int out_size)
{
    const float* inp = (const float*)d_in[0];
    const float* w1  = (const float*)d_in[1];
    const float* b1  = (const float*)d_in[2];
    const float* w2  = (const float*)d_in[3];
    const float* b2  = (const float*)d_in[4];
    const float* w3  = (const float*)d_in[5];
    const float* b3  = (const float*)d_in[6];
    const float* wp  = (const float*)d_in[7];
    const float* bp  = (const float*)d_in[8];
    const float* wr  = (const float*)d_in[9];
    const float* br  = (const float*)d_in[10];
    float* out = (float*)d_out;
    (void)in_sizes; (void)n_in; (void)out_size;

    Meta m;
    int ns = 0;
    {
        double s = 12.0 / 20.0, mm = s * 1080.0;
        while (mm >= 12.0 && ns < NS) {
            m.hs[ns]   = (int)ceil(1080.0 * s);
            m.inv[ns]  = (float)(1080.0 / (double)m.hs[ns]);
            m.rinv[ns] = (float)((double)m.hs[ns] / 1080.0);
            m.scl[ns]  = (float)s;
            ns++;
            s *= 0.709; mm *= 0.709;
        }
    }

    int oT = 0, oI = 0, oP = 0, oC = 0, ntot = 0;
    m.bsRH[0] = m.bsRV[0] = m.bsCP[0] = m.bsC2[0] = m.bsC3[0] = 0;
    for (int k = 0; k < ns; k++) {
        int hs = m.hs[k], ws = hs;
        int h1 = hs - 2;
        int h2 = (h1 + 1) / 2, w2d = h2;
        int h3 = h2 - 2, w3d = h3;
        int h4 = h3 - 2, w4 = h4;

        m.offT[k] = oT;  oT += BATCH * HIN * ws * 3;
        m.offI[k] = oI;  oI += BATCH * hs * ws * 3;
        m.offP[k] = oP;  oP += BATCH * h2 * w2d * 10;
        m.offC[k] = oC;  oC += BATCH * h3 * w3d * 16;
        m.noff[k] = ntot; ntot += h4 * w4;

        int T;
        T = BATCH * HIN * ws;                 m.bsRH[k+1] = m.bsRH[k] + (T + 255) / 256;
        T = BATCH * hs * ws;                  m.bsRV[k+1] = m.bsRV[k] + (T + 255) / 256;
        T = BATCH * h2 * w2d;                 m.bsCP[k+1] = m.bsCP[k] + (T + 127) / 128;
        T = BATCH * h3 * ((w2d - 2 + 3) / 4); m.bsC2[k+1] = m.bsC2[k] + (T + 127) / 128;
        T = BATCH * h4 * ((w4 + 1) / 2);      m.bsC3[k+1] = m.bsC3[k] + (T + 127) / 128;
    }
    m.ntot = ntot;
    for (int k = ns; k < NS; k++) {
        m.hs[k] = m.hs[ns-1]; m.inv[k] = m.inv[ns-1];
        m.rinv[k] = m.rinv[ns-1]; m.scl[k] = m.scl[ns-1];
        m.offT[k] = m.offI[k] = m.offP[k] = m.offC[k] = 0; m.noff[k] = 0;
        m.bsRH[k+1] = m.bsRH[k]; m.bsRV[k+1] = m.bsRV[k];
        m.bsCP[k+1] = m.bsCP[k]; m.bsC2[k+1] = m.bsC2[k]; m.bsC3[k+1] = m.bsC3[k];
        m.bsRH[k] = 0x7fffffff; m.bsRV[k] = 0x7fffffff; m.bsCP[k] = 0x7fffffff;
        m.bsC2[k] = 0x7fffffff; m.bsC3[k] = 0x7fffffff;
    }

    k_resize_h <<<m.bsRH[ns], 256>>>(inp, m);
    k_resize_v <<<m.bsRV[ns], 256>>>(m);
    k_conv1pool<<<m.bsCP[ns], 128>>>(w1, b1, m);
    k_conv2    <<<m.bsC2[ns], 128>>>(w2, b2, m);
    k_conv3head<<<m.bsC3[ns], 128>>>(w3, b3, wp, bp, wr, br, out, m);
}